// round 14
// baseline (speedup 1.0000x reference)
#include <cuda_runtime.h>
#include <cuda_bf16.h>
#include <cstdint>

// MoE gather-combine: out[t, :] = sum_k scores[t*K+k] * flat[slots[t*K+k], :]
// Experiment: fetch each gathered 8KB row with ONE cp.async.bulk
// (global->shared, mbarrier completion) instead of 64 per-warp LDG.128
// requests. The DRAM controller sees two maximal sequential bursts per CTA
// -> probes whether request coherence improves mixed r/w DRAM efficiency.
// Combine from SMEM, streaming .cs stores. 1 CTA/token, 256 thr, 8 CTA/SM.

__device__ __forceinline__ uint32_t smem_u32(const void* p) {
    uint32_t a;
    asm("{ .reg .u64 t; cvta.to.shared.u64 t, %1; cvt.u32.u64 %0, t; }"
        : "=r"(a) : "l"(p));
    return a;
}

__device__ __forceinline__ void stcs_f4(float4* p, float4 v) {
    asm volatile("st.global.cs.v4.f32 [%0], {%1,%2,%3,%4};"
                 :: "l"(p), "f"(v.x), "f"(v.y), "f"(v.z), "f"(v.w) : "memory");
}

__device__ __forceinline__ void bulk_ld(uint32_t dst_smem, const void* src, uint32_t bytes, uint32_t mbar) {
    asm volatile("cp.async.bulk.shared::cta.global.mbarrier::complete_tx::bytes "
                 "[%0], [%1], %2, [%3];"
                 :: "r"(dst_smem), "l"(src), "r"(bytes), "r"(mbar) : "memory");
}

__global__ void __launch_bounds__(256, 8)
moe_gather_h2048_bulk(const float* __restrict__ flat,
                      const float* __restrict__ scores,
                      const int* __restrict__ slots,
                      const int* __restrict__ topk_p,
                      float* __restrict__ out,
                      int n_tokens) {
    __shared__ alignas(128) float buf[2][2048];   // 16 KB
    __shared__ alignas(8) unsigned long long mbar_storage;

    const int token = blockIdx.x;
    if (token >= n_tokens) return;
    const int K = topk_p[0];

    const int t0 = threadIdx.x;          // float4 lane 0..255
    const int t1 = threadIdx.x + 256;    // float4 lane 256..511
    float4* orow = reinterpret_cast<float4*>(out + (size_t)token * 2048);

    if (K == 2) {
        const int   s0 = __ldg(&slots[token * 2 + 0]);
        const int   s1 = __ldg(&slots[token * 2 + 1]);
        const float w0 = __ldg(&scores[token * 2 + 0]);
        const float w1 = __ldg(&scores[token * 2 + 1]);

        const uint32_t mbar = smem_u32(&mbar_storage);
        if (threadIdx.x == 0) {
            asm volatile("mbarrier.init.shared.b64 [%0], %1;" :: "r"(mbar), "r"(1) : "memory");
            asm volatile("fence.proxy.async.shared::cta;" ::: "memory");
            asm volatile("mbarrier.arrive.expect_tx.shared.b64 _, [%0], %1;"
                         :: "r"(mbar), "r"(16384) : "memory");
            bulk_ld(smem_u32(buf[0]), flat + (size_t)s0 * 2048, 8192, mbar);
            bulk_ld(smem_u32(buf[1]), flat + (size_t)s1 * 2048, 8192, mbar);
        }
        __syncthreads();   // mbarrier init visible to all before waiting

        // Wait for both bulk copies (phase 0, single-shot barrier).
        uint32_t done = 0;
        while (!done) {
            asm volatile("{ .reg .pred p; "
                         "mbarrier.try_wait.parity.shared.b64 p, [%1], %2; "
                         "selp.b32 %0, 1, 0, p; }"
                         : "=r"(done) : "r"(mbar), "r"(0) : "memory");
        }

        const float4* b0p = reinterpret_cast<const float4*>(buf[0]);
        const float4* b1p = reinterpret_cast<const float4*>(buf[1]);
        float4 a0 = b0p[t0];
        float4 a1 = b0p[t1];
        float4 b0 = b1p[t0];
        float4 b1 = b1p[t1];

        float4 acc0, acc1;
        acc0.x = fmaf(w1, b0.x, w0 * a0.x);
        acc0.y = fmaf(w1, b0.y, w0 * a0.y);
        acc0.z = fmaf(w1, b0.z, w0 * a0.z);
        acc0.w = fmaf(w1, b0.w, w0 * a0.w);
        acc1.x = fmaf(w1, b1.x, w0 * a1.x);
        acc1.y = fmaf(w1, b1.y, w0 * a1.y);
        acc1.z = fmaf(w1, b1.z, w0 * a1.z);
        acc1.w = fmaf(w1, b1.w, w0 * a1.w);

        stcs_f4(&orow[t0], acc0);
        stcs_f4(&orow[t1], acc1);
        return;
    }

    // Generic K path: plain LDG version (correct for any K).
    float4 acc0 = make_float4(0.f, 0.f, 0.f, 0.f);
    float4 acc1 = make_float4(0.f, 0.f, 0.f, 0.f);
    for (int k = 0; k < K; ++k) {
        const int   slot = __ldg(&slots[token * K + k]);
        const float w    = __ldg(&scores[token * K + k]);
        const float4* row = reinterpret_cast<const float4*>(flat + (size_t)slot * 2048);
        float4 v0 = __ldg(&row[t0]);
        float4 v1 = __ldg(&row[t1]);
        acc0.x = fmaf(w, v0.x, acc0.x);
        acc0.y = fmaf(w, v0.y, acc0.y);
        acc0.z = fmaf(w, v0.z, acc0.z);
        acc0.w = fmaf(w, v0.w, acc0.w);
        acc1.x = fmaf(w, v1.x, acc1.x);
        acc1.y = fmaf(w, v1.y, acc1.y);
        acc1.z = fmaf(w, v1.z, acc1.z);
        acc1.w = fmaf(w, v1.w, acc1.w);
    }
    stcs_f4(&orow[t0], acc0);
    stcs_f4(&orow[t1], acc1);
}

// Generic fallback for any hidden (scalar loop within row).
__global__ void moe_gather_generic_kernel(const float* __restrict__ flat,
                                          const float* __restrict__ scores,
                                          const int* __restrict__ slots,
                                          const int* __restrict__ topk_p,
                                          float* __restrict__ out,
                                          int n_tokens, int hidden) {
    const int token = blockIdx.x;
    if (token >= n_tokens) return;
    const int K = topk_p[0];

    for (int h = threadIdx.x; h < hidden; h += blockDim.x) {
        float acc = 0.f;
        for (int k = 0; k < K; ++k) {
            const int   slot = slots[token * K + k];
            const float w    = scores[token * K + k];
            acc = fmaf(w, flat[(size_t)slot * hidden + h], acc);
        }
        out[(size_t)token * hidden + h] = acc;
    }
}

extern "C" void kernel_launch(void* const* d_in, const int* in_sizes, int n_in,
                              void* d_out, int out_size) {
    const float* flat   = (const float*)d_in[0];   // moe_output, [n_slots, hidden]
    const float* scores = (const float*)d_in[1];   // [n_slots]
    const int*   slots  = (const int*)d_in[2];     // [n_slots]
    const int*   topk_p = (const int*)d_in[3];     // scalar top_k (device)

    const int n_slots = in_sizes[1];
    const int hidden  = in_sizes[0] / n_slots;
    const int n_tokens = out_size / hidden;

    float* out = (float*)d_out;

    if (hidden == 2048) {
        moe_gather_h2048_bulk<<<n_tokens, 256>>>(flat, scores, slots, topk_p,
                                                 out, n_tokens);
    } else {
        moe_gather_generic_kernel<<<n_tokens, 256>>>(flat, scores, slots, topk_p,
                                                     out, n_tokens, hidden);
    }
}

// round 15
// speedup vs baseline: 1.0491x; 1.0491x over previous
#include <cuda_runtime.h>
#include <cuda_bf16.h>

// MoE gather-combine: out[t, :] = sum_k scores[t*K+k] * flat[slots[t*K+k], :]
// FINAL (best of 14 measured rounds = R5 config): 1 CTA per token, 256
// threads, 2 float4/thread/row -> K=2 gives 4 independent LDG.128 in
// flight per thread at ~80-84% occupancy.
//
// Exhaustive search summary (kernel us):
//   THIS config: 23.8-24.2 (optimum)     | deeper ILP 8 ld/thr,128t: 26.9
//   narrower split2 (2 ld/thr): 27.6     | persistent(+idx prefetch): 24.4
//   L2 row prefetch: 30.7                | v8 256-bit loads: 24.4
//   cp.async.bulk 8KB bursts: 24.3       | .wt stores: +7MB DRAM, no gain
// Store sweep: default 24.6 > .cs 23.8 < .wt 24.1 -> .cs.
// Fetch-path-independence (LDG.128 == LDG.256 == TMA bulk, all ~4.85TB/s)
// proves ~61% of spec HBM is the DRAM efficiency ceiling for this mixed
// random-8KB-gather-read + streaming-write pattern. Traffic (~117MB) is
// compulsory; L2 carveout is 0 and cudaDeviceSetLimit is banned, so L2
// retention is not controllable. Nothing SM-side moves the wall.

__device__ __forceinline__ unsigned long long mk_evict_last_policy() {
    unsigned long long pol;
    asm("createpolicy.fractional.L2::evict_last.b64 %0, 1.0;" : "=l"(pol));
    return pol;
}

__device__ __forceinline__ float4 ldg_el_f4(const float4* p, unsigned long long pol) {
    float4 v;
    asm volatile("ld.global.nc.L2::cache_hint.v4.f32 {%0,%1,%2,%3}, [%4], %5;"
                 : "=f"(v.x), "=f"(v.y), "=f"(v.z), "=f"(v.w)
                 : "l"(p), "l"(pol));
    return v;
}

__device__ __forceinline__ void stcs_f4(float4* p, float4 v) {
    asm volatile("st.global.cs.v4.f32 [%0], {%1,%2,%3,%4};"
                 :: "l"(p), "f"(v.x), "f"(v.y), "f"(v.z), "f"(v.w) : "memory");
}

__global__ void __launch_bounds__(256, 8)
moe_gather_h2048_kernel(const float* __restrict__ flat,
                        const float* __restrict__ scores,
                        const int* __restrict__ slots,
                        const int* __restrict__ topk_p,
                        float* __restrict__ out,
                        int n_tokens) {
    const int token = blockIdx.x;
    if (token >= n_tokens) return;
    const int K = topk_p[0];
    const unsigned long long pol = mk_evict_last_policy();

    const int t0 = threadIdx.x;          // float4 lane 0..255
    const int t1 = threadIdx.x + 256;    // float4 lane 256..511
    float4* orow = reinterpret_cast<float4*>(out + (size_t)token * 2048);

    if (K == 2) {
        const int   s0 = __ldg(&slots[token * 2 + 0]);
        const int   s1 = __ldg(&slots[token * 2 + 1]);
        const float w0 = __ldg(&scores[token * 2 + 0]);
        const float w1 = __ldg(&scores[token * 2 + 1]);

        const float4* r0 = reinterpret_cast<const float4*>(flat + (size_t)s0 * 2048);
        const float4* r1 = reinterpret_cast<const float4*>(flat + (size_t)s1 * 2048);

        // 4 independent LDG.128, all in flight before any FMA.
        float4 a0 = ldg_el_f4(&r0[t0], pol);
        float4 a1 = ldg_el_f4(&r0[t1], pol);
        float4 b0 = ldg_el_f4(&r1[t0], pol);
        float4 b1 = ldg_el_f4(&r1[t1], pol);

        float4 acc0, acc1;
        acc0.x = fmaf(w1, b0.x, w0 * a0.x);
        acc0.y = fmaf(w1, b0.y, w0 * a0.y);
        acc0.z = fmaf(w1, b0.z, w0 * a0.z);
        acc0.w = fmaf(w1, b0.w, w0 * a0.w);
        acc1.x = fmaf(w1, b1.x, w0 * a1.x);
        acc1.y = fmaf(w1, b1.y, w0 * a1.y);
        acc1.z = fmaf(w1, b1.z, w0 * a1.z);
        acc1.w = fmaf(w1, b1.w, w0 * a1.w);

        stcs_f4(&orow[t0], acc0);
        stcs_f4(&orow[t1], acc1);
        return;
    }

    // Generic K path.
    float4 acc0 = make_float4(0.f, 0.f, 0.f, 0.f);
    float4 acc1 = make_float4(0.f, 0.f, 0.f, 0.f);
    for (int k = 0; k < K; ++k) {
        const int   slot = __ldg(&slots[token * K + k]);
        const float w    = __ldg(&scores[token * K + k]);
        const float4* row = reinterpret_cast<const float4*>(flat + (size_t)slot * 2048);
        float4 v0 = ldg_el_f4(&row[t0], pol);
        float4 v1 = ldg_el_f4(&row[t1], pol);
        acc0.x = fmaf(w, v0.x, acc0.x);
        acc0.y = fmaf(w, v0.y, acc0.y);
        acc0.z = fmaf(w, v0.z, acc0.z);
        acc0.w = fmaf(w, v0.w, acc0.w);
        acc1.x = fmaf(w, v1.x, acc1.x);
        acc1.y = fmaf(w, v1.y, acc1.y);
        acc1.z = fmaf(w, v1.z, acc1.z);
        acc1.w = fmaf(w, v1.w, acc1.w);
    }
    stcs_f4(&orow[t0], acc0);
    stcs_f4(&orow[t1], acc1);
}

// Generic fallback for any hidden (scalar loop within row).
__global__ void moe_gather_generic_kernel(const float* __restrict__ flat,
                                          const float* __restrict__ scores,
                                          const int* __restrict__ slots,
                                          const int* __restrict__ topk_p,
                                          float* __restrict__ out,
                                          int n_tokens, int hidden) {
    const int token = blockIdx.x;
    if (token >= n_tokens) return;
    const int K = topk_p[0];

    for (int h = threadIdx.x; h < hidden; h += blockDim.x) {
        float acc = 0.f;
        for (int k = 0; k < K; ++k) {
            const int   slot = slots[token * K + k];
            const float w    = scores[token * K + k];
            acc = fmaf(w, flat[(size_t)slot * hidden + h], acc);
        }
        out[(size_t)token * hidden + h] = acc;
    }
}

extern "C" void kernel_launch(void* const* d_in, const int* in_sizes, int n_in,
                              void* d_out, int out_size) {
    const float* flat   = (const float*)d_in[0];   // moe_output, [n_slots, hidden]
    const float* scores = (const float*)d_in[1];   // [n_slots]
    const int*   slots  = (const int*)d_in[2];     // [n_slots]
    const int*   topk_p = (const int*)d_in[3];     // scalar top_k (device)

    const int n_slots = in_sizes[1];
    const int hidden  = in_sizes[0] / n_slots;
    const int n_tokens = out_size / hidden;

    float* out = (float*)d_out;

    if (hidden == 2048) {
        moe_gather_h2048_kernel<<<n_tokens, 256>>>(flat, scores, slots, topk_p,
                                                   out, n_tokens);
    } else {
        moe_gather_generic_kernel<<<n_tokens, 256>>>(flat, scores, slots, topk_p,
                                                     out, n_tokens, hidden);
    }
}

// round 16
// speedup vs baseline: 1.0590x; 1.0094x over previous
#include <cuda_runtime.h>
#include <cuda_bf16.h>

// MoE gather-combine: out[t, :] = sum_k scores[t*K+k] * flat[slots[t*K+k], :]
// FINAL (optimum of 15 measured rounds; reproduced 4x at 23.8-24.2us
// kernel / 27.1-27.5us e2e): 1 CTA per token, 256 threads, 2 float4 per
// thread per row -> K=2 gives 4 independent LDG.128 in flight per thread
// at ~82% occupancy.
//
// Exhaustive search summary (kernel us):
//   THIS config: 23.8-24.2 (optimum)     | deeper ILP 8 ld/thr,128t: 26.9
//   narrower split2 (2 ld/thr): 27.6     | persistent(+idx prefetch): 24.4
//   L2 row prefetch: 30.7                | v8 256-bit loads: 24.4
//   cp.async.bulk 8KB bursts: 24.3       | .wt stores: +7MB DRAM, no gain
// Store sweep: default 24.6 > .cs 23.8 < .wt 24.1 -> .cs.
// Fetch-path independence (LDG.128 == LDG.256 == TMA bulk, all ~4.85TB/s)
// proves ~61% of spec HBM is the DRAM efficiency ceiling for this mixed
// random-8KB-gather-read + streaming-write pattern. Traffic (~117MB) is
// compulsory; L2 carveout is 0 and cudaDeviceSetLimit is banned, so L2
// retention is not controllable. Nothing SM-side moves the wall.

__device__ __forceinline__ unsigned long long mk_evict_last_policy() {
    unsigned long long pol;
    asm("createpolicy.fractional.L2::evict_last.b64 %0, 1.0;" : "=l"(pol));
    return pol;
}

__device__ __forceinline__ float4 ldg_el_f4(const float4* p, unsigned long long pol) {
    float4 v;
    asm volatile("ld.global.nc.L2::cache_hint.v4.f32 {%0,%1,%2,%3}, [%4], %5;"
                 : "=f"(v.x), "=f"(v.y), "=f"(v.z), "=f"(v.w)
                 : "l"(p), "l"(pol));
    return v;
}

__device__ __forceinline__ void stcs_f4(float4* p, float4 v) {
    asm volatile("st.global.cs.v4.f32 [%0], {%1,%2,%3,%4};"
                 :: "l"(p), "f"(v.x), "f"(v.y), "f"(v.z), "f"(v.w) : "memory");
}

__global__ void __launch_bounds__(256, 8)
moe_gather_h2048_kernel(const float* __restrict__ flat,
                        const float* __restrict__ scores,
                        const int* __restrict__ slots,
                        const int* __restrict__ topk_p,
                        float* __restrict__ out,
                        int n_tokens) {
    const int token = blockIdx.x;
    if (token >= n_tokens) return;
    const int K = topk_p[0];
    const unsigned long long pol = mk_evict_last_policy();

    const int t0 = threadIdx.x;          // float4 lane 0..255
    const int t1 = threadIdx.x + 256;    // float4 lane 256..511
    float4* orow = reinterpret_cast<float4*>(out + (size_t)token * 2048);

    if (K == 2) {
        const int   s0 = __ldg(&slots[token * 2 + 0]);
        const int   s1 = __ldg(&slots[token * 2 + 1]);
        const float w0 = __ldg(&scores[token * 2 + 0]);
        const float w1 = __ldg(&scores[token * 2 + 1]);

        const float4* r0 = reinterpret_cast<const float4*>(flat + (size_t)s0 * 2048);
        const float4* r1 = reinterpret_cast<const float4*>(flat + (size_t)s1 * 2048);

        // 4 independent LDG.128, all in flight before any FMA.
        float4 a0 = ldg_el_f4(&r0[t0], pol);
        float4 a1 = ldg_el_f4(&r0[t1], pol);
        float4 b0 = ldg_el_f4(&r1[t0], pol);
        float4 b1 = ldg_el_f4(&r1[t1], pol);

        float4 acc0, acc1;
        acc0.x = fmaf(w1, b0.x, w0 * a0.x);
        acc0.y = fmaf(w1, b0.y, w0 * a0.y);
        acc0.z = fmaf(w1, b0.z, w0 * a0.z);
        acc0.w = fmaf(w1, b0.w, w0 * a0.w);
        acc1.x = fmaf(w1, b1.x, w0 * a1.x);
        acc1.y = fmaf(w1, b1.y, w0 * a1.y);
        acc1.z = fmaf(w1, b1.z, w0 * a1.z);
        acc1.w = fmaf(w1, b1.w, w0 * a1.w);

        stcs_f4(&orow[t0], acc0);
        stcs_f4(&orow[t1], acc1);
        return;
    }

    // Generic K path.
    float4 acc0 = make_float4(0.f, 0.f, 0.f, 0.f);
    float4 acc1 = make_float4(0.f, 0.f, 0.f, 0.f);
    for (int k = 0; k < K; ++k) {
        const int   slot = __ldg(&slots[token * K + k]);
        const float w    = __ldg(&scores[token * K + k]);
        const float4* row = reinterpret_cast<const float4*>(flat + (size_t)slot * 2048);
        float4 v0 = ldg_el_f4(&row[t0], pol);
        float4 v1 = ldg_el_f4(&row[t1], pol);
        acc0.x = fmaf(w, v0.x, acc0.x);
        acc0.y = fmaf(w, v0.y, acc0.y);
        acc0.z = fmaf(w, v0.z, acc0.z);
        acc0.w = fmaf(w, v0.w, acc0.w);
        acc1.x = fmaf(w, v1.x, acc1.x);
        acc1.y = fmaf(w, v1.y, acc1.y);
        acc1.z = fmaf(w, v1.z, acc1.z);
        acc1.w = fmaf(w, v1.w, acc1.w);
    }
    stcs_f4(&orow[t0], acc0);
    stcs_f4(&orow[t1], acc1);
}

// Generic fallback for any hidden (scalar loop within row).
__global__ void moe_gather_generic_kernel(const float* __restrict__ flat,
                                          const float* __restrict__ scores,
                                          const int* __restrict__ slots,
                                          const int* __restrict__ topk_p,
                                          float* __restrict__ out,
                                          int n_tokens, int hidden) {
    const int token = blockIdx.x;
    if (token >= n_tokens) return;
    const int K = topk_p[0];

    for (int h = threadIdx.x; h < hidden; h += blockDim.x) {
        float acc = 0.f;
        for (int k = 0; k < K; ++k) {
            const int   slot = slots[token * K + k];
            const float w    = scores[token * K + k];
            acc = fmaf(w, flat[(size_t)slot * hidden + h], acc);
        }
        out[(size_t)token * hidden + h] = acc;
    }
}

extern "C" void kernel_launch(void* const* d_in, const int* in_sizes, int n_in,
                              void* d_out, int out_size) {
    const float* flat   = (const float*)d_in[0];   // moe_output, [n_slots, hidden]
    const float* scores = (const float*)d_in[1];   // [n_slots]
    const int*   slots  = (const int*)d_in[2];     // [n_slots]
    const int*   topk_p = (const int*)d_in[3];     // scalar top_k (device)

    const int n_slots = in_sizes[1];
    const int hidden  = in_sizes[0] / n_slots;
    const int n_tokens = out_size / hidden;

    float* out = (float*)d_out;

    if (hidden == 2048) {
        moe_gather_h2048_kernel<<<n_tokens, 256>>>(flat, scores, slots, topk_p,
                                                   out, n_tokens);
    } else {
        moe_gather_generic_kernel<<<n_tokens, 256>>>(flat, scores, slots, topk_p,
                                                     out, n_tokens, hidden);
    }
}

// round 17
// speedup vs baseline: 1.0602x; 1.0012x over previous
#include <cuda_runtime.h>
#include <cuda_bf16.h>

// MoE gather-combine: out[t, :] = sum_k scores[t*K+k] * flat[slots[t*K+k], :]
// FINAL (optimum of 16 measured rounds; reproduced 5x at 23.8-24.2us
// kernel / 27.1-27.5us e2e): 1 CTA per token, 256 threads, 2 float4 per
// thread per row -> K=2 gives 4 independent LDG.128 in flight per thread
// at ~82% occupancy.
//
// Exhaustive search summary (kernel us):
//   THIS config: 23.8-24.2 (optimum)     | deeper ILP 8 ld/thr,128t: 26.9
//   narrower split2 (2 ld/thr): 27.6     | persistent(+idx prefetch): 24.4
//   L2 row prefetch: 30.7                | v8 256-bit loads: 24.4
//   cp.async.bulk 8KB bursts: 24.3       | .wt stores: +7MB DRAM, no gain
// Store sweep: default 24.6 > .cs 23.8 < .wt 24.1 -> .cs.
// Fetch-path independence (LDG.128 == LDG.256 == TMA bulk, all ~4.85TB/s)
// proves ~61% of spec HBM is the DRAM efficiency ceiling for this mixed
// random-8KB-gather-read + streaming-write pattern. Traffic (~117MB) is
// compulsory; L2 carveout is 0 and cudaDeviceSetLimit is banned, so L2
// retention is not controllable. Nothing SM-side moves the wall.

__device__ __forceinline__ unsigned long long mk_evict_last_policy() {
    unsigned long long pol;
    asm("createpolicy.fractional.L2::evict_last.b64 %0, 1.0;" : "=l"(pol));
    return pol;
}

__device__ __forceinline__ float4 ldg_el_f4(const float4* p, unsigned long long pol) {
    float4 v;
    asm volatile("ld.global.nc.L2::cache_hint.v4.f32 {%0,%1,%2,%3}, [%4], %5;"
                 : "=f"(v.x), "=f"(v.y), "=f"(v.z), "=f"(v.w)
                 : "l"(p), "l"(pol));
    return v;
}

__device__ __forceinline__ void stcs_f4(float4* p, float4 v) {
    asm volatile("st.global.cs.v4.f32 [%0], {%1,%2,%3,%4};"
                 :: "l"(p), "f"(v.x), "f"(v.y), "f"(v.z), "f"(v.w) : "memory");
}

__global__ void __launch_bounds__(256, 8)
moe_gather_h2048_kernel(const float* __restrict__ flat,
                        const float* __restrict__ scores,
                        const int* __restrict__ slots,
                        const int* __restrict__ topk_p,
                        float* __restrict__ out,
                        int n_tokens) {
    const int token = blockIdx.x;
    if (token >= n_tokens) return;
    const int K = topk_p[0];
    const unsigned long long pol = mk_evict_last_policy();

    const int t0 = threadIdx.x;          // float4 lane 0..255
    const int t1 = threadIdx.x + 256;    // float4 lane 256..511
    float4* orow = reinterpret_cast<float4*>(out + (size_t)token * 2048);

    if (K == 2) {
        const int   s0 = __ldg(&slots[token * 2 + 0]);
        const int   s1 = __ldg(&slots[token * 2 + 1]);
        const float w0 = __ldg(&scores[token * 2 + 0]);
        const float w1 = __ldg(&scores[token * 2 + 1]);

        const float4* r0 = reinterpret_cast<const float4*>(flat + (size_t)s0 * 2048);
        const float4* r1 = reinterpret_cast<const float4*>(flat + (size_t)s1 * 2048);

        // 4 independent LDG.128, all in flight before any FMA.
        float4 a0 = ldg_el_f4(&r0[t0], pol);
        float4 a1 = ldg_el_f4(&r0[t1], pol);
        float4 b0 = ldg_el_f4(&r1[t0], pol);
        float4 b1 = ldg_el_f4(&r1[t1], pol);

        float4 acc0, acc1;
        acc0.x = fmaf(w1, b0.x, w0 * a0.x);
        acc0.y = fmaf(w1, b0.y, w0 * a0.y);
        acc0.z = fmaf(w1, b0.z, w0 * a0.z);
        acc0.w = fmaf(w1, b0.w, w0 * a0.w);
        acc1.x = fmaf(w1, b1.x, w0 * a1.x);
        acc1.y = fmaf(w1, b1.y, w0 * a1.y);
        acc1.z = fmaf(w1, b1.z, w0 * a1.z);
        acc1.w = fmaf(w1, b1.w, w0 * a1.w);

        stcs_f4(&orow[t0], acc0);
        stcs_f4(&orow[t1], acc1);
        return;
    }

    // Generic K path.
    float4 acc0 = make_float4(0.f, 0.f, 0.f, 0.f);
    float4 acc1 = make_float4(0.f, 0.f, 0.f, 0.f);
    for (int k = 0; k < K; ++k) {
        const int   slot = __ldg(&slots[token * K + k]);
        const float w    = __ldg(&scores[token * K + k]);
        const float4* row = reinterpret_cast<const float4*>(flat + (size_t)slot * 2048);
        float4 v0 = ldg_el_f4(&row[t0], pol);
        float4 v1 = ldg_el_f4(&row[t1], pol);
        acc0.x = fmaf(w, v0.x, acc0.x);
        acc0.y = fmaf(w, v0.y, acc0.y);
        acc0.z = fmaf(w, v0.z, acc0.z);
        acc0.w = fmaf(w, v0.w, acc0.w);
        acc1.x = fmaf(w, v1.x, acc1.x);
        acc1.y = fmaf(w, v1.y, acc1.y);
        acc1.z = fmaf(w, v1.z, acc1.z);
        acc1.w = fmaf(w, v1.w, acc1.w);
    }
    stcs_f4(&orow[t0], acc0);
    stcs_f4(&orow[t1], acc1);
}

// Generic fallback for any hidden (scalar loop within row).
__global__ void moe_gather_generic_kernel(const float* __restrict__ flat,
                                          const float* __restrict__ scores,
                                          const int* __restrict__ slots,
                                          const int* __restrict__ topk_p,
                                          float* __restrict__ out,
                                          int n_tokens, int hidden) {
    const int token = blockIdx.x;
    if (token >= n_tokens) return;
    const int K = topk_p[0];

    for (int h = threadIdx.x; h < hidden; h += blockDim.x) {
        float acc = 0.f;
        for (int k = 0; k < K; ++k) {
            const int   slot = slots[token * K + k];
            const float w    = scores[token * K + k];
            acc = fmaf(w, flat[(size_t)slot * hidden + h], acc);
        }
        out[(size_t)token * hidden + h] = acc;
    }
}

extern "C" void kernel_launch(void* const* d_in, const int* in_sizes, int n_in,
                              void* d_out, int out_size) {
    const float* flat   = (const float*)d_in[0];   // moe_output, [n_slots, hidden]
    const float* scores = (const float*)d_in[1];   // [n_slots]
    const int*   slots  = (const int*)d_in[2];     // [n_slots]
    const int*   topk_p = (const int*)d_in[3];     // scalar top_k (device)

    const int n_slots = in_sizes[1];
    const int hidden  = in_sizes[0] / n_slots;
    const int n_tokens = out_size / hidden;

    float* out = (float*)d_out;

    if (hidden == 2048) {
        moe_gather_h2048_kernel<<<n_tokens, 256>>>(flat, scores, slots, topk_p,
                                                   out, n_tokens);
    } else {
        moe_gather_generic_kernel<<<n_tokens, 256>>>(flat, scores, slots, topk_p,
                                                     out, n_tokens, hidden);
    }
}